// round 1
// baseline (speedup 1.0000x reference)
#include <cuda_runtime.h>

#define NUM_JOINT 19
#define ROOT_SCALE 200.0f
#define BLOCK 128
#define ROWLEN 76            // floats per batch element (in AND out)
#define STRIDE 77            // padded smem row stride (odd -> conflict-free)

__global__ __launch_bounds__(BLOCK)
void fk_kernel(const float* __restrict__ root,
               const float* __restrict__ joint,
               const float* __restrict__ offsets,
               float* __restrict__ out)
{
    __shared__ float s[BLOCK * STRIDE];
    const int t = threadIdx.x;
    const long long base = (long long)blockIdx.x * (BLOCK * ROWLEN);

    // Coalesced stage-in: 76 floats per element, contiguous across block.
    #pragma unroll
    for (int i = 0; i < ROWLEN; i++) {
        int idx = t + i * BLOCK;                 // 0 .. BLOCK*76-1
        int r = idx / ROWLEN, c = idx % ROWLEN;  // const-div -> mul/shift
        s[r * STRIDE + c] = joint[base + idx];
    }
    __syncthreads();

    const int b = blockIdx.x * BLOCK + t;
    const float rx = root[b * 3 + 0] * ROOT_SCALE;
    const float ry = root[b * 3 + 1] * ROOT_SCALE;
    const float rz = root[b * 3 + 2] * ROOT_SCALE;

    float Rm[NUM_JOINT][9];
    float pm[NUM_JOINT][3];
    const int parents[NUM_JOINT] = {-1,0,1,2,3,2,5,6,7,2,9,10,11,0,13,14,0,16,17};
    float* row = &s[t * STRIDE];

    #pragma unroll
    for (int j = 0; j < NUM_JOINT; j++) {
        const float w = row[j * 4 + 0];
        const float x = row[j * 4 + 1];
        const float y = row[j * 4 + 2];
        const float z = row[j * 4 + 3];
        const float ts = 2.0f / (w * w + x * x + y * y + z * z);

        float R[9];
        R[0] = 1.0f - ts * (y * y + z * z);
        R[1] = ts * (x * y - z * w);
        R[2] = ts * (x * z + y * w);
        R[3] = ts * (x * y + z * w);
        R[4] = 1.0f - ts * (x * x + z * z);
        R[5] = ts * (y * z - x * w);
        R[6] = ts * (x * z - y * w);
        R[7] = ts * (y * z + x * w);
        R[8] = 1.0f - ts * (x * x + y * y);

        // offsets are identity rotation + translation (per reference setup):
        // RT = [R | R*t]; chain as affine (rotation, position) pairs.
        const float tx = __ldg(&offsets[j * 16 + 3]);
        const float ty = __ldg(&offsets[j * 16 + 7]);
        const float tz = __ldg(&offsets[j * 16 + 11]);
        const float plx = R[0] * tx + R[1] * ty + R[2] * tz;
        const float ply = R[3] * tx + R[4] * ty + R[5] * tz;
        const float plz = R[6] * tx + R[7] * ty + R[8] * tz;

        if (j == 0) {
            #pragma unroll
            for (int k = 0; k < 9; k++) Rm[0][k] = R[k];
            pm[0][0] = plx; pm[0][1] = ply; pm[0][2] = plz;
        } else {
            const int p = parents[j];
            #pragma unroll
            for (int r = 0; r < 3; r++) {
                #pragma unroll
                for (int c = 0; c < 3; c++) {
                    Rm[j][r * 3 + c] = Rm[p][r * 3 + 0] * R[0 + c]
                                     + Rm[p][r * 3 + 1] * R[3 + c]
                                     + Rm[p][r * 3 + 2] * R[6 + c];
                }
            }
            pm[j][0] = Rm[p][0] * plx + Rm[p][1] * ply + Rm[p][2] * plz + pm[p][0];
            pm[j][1] = Rm[p][3] * plx + Rm[p][4] * ply + Rm[p][5] * plz + pm[p][1];
            pm[j][2] = Rm[p][6] * plx + Rm[p][7] * ply + Rm[p][8] * plz + pm[p][2];
        }

        // In-place: position j (xyz,1 + scaled root) overwrites quaternion j.
        row[j * 4 + 0] = pm[j][0] + rx;
        row[j * 4 + 1] = pm[j][1] + ry;
        row[j * 4 + 2] = pm[j][2] + rz;
        row[j * 4 + 3] = 1.0f;
    }
    __syncthreads();

    // Coalesced stage-out.
    #pragma unroll
    for (int i = 0; i < ROWLEN; i++) {
        int idx = t + i * BLOCK;
        int r = idx / ROWLEN, c = idx % ROWLEN;
        out[base + idx] = s[r * STRIDE + c];
    }
}

extern "C" void kernel_launch(void* const* d_in, const int* in_sizes, int n_in,
                              void* d_out, int out_size)
{
    const float* root    = (const float*)d_in[0];   // (B, 3)
    const float* joint   = (const float*)d_in[1];   // (B, 76)
    const float* offsets = (const float*)d_in[2];   // (19, 4, 4)
    float* out = (float*)d_out;                     // (B, 19, 4)

    const int B = in_sizes[1] / (NUM_JOINT * 4);
    const int grid = (B + BLOCK - 1) / BLOCK;
    fk_kernel<<<grid, BLOCK>>>(root, joint, offsets, out);
}